// round 13
// baseline (speedup 1.0000x reference)
#include <cuda_runtime.h>
#include <stdint.h>
#include <math.h>

#define H 64
#define WARPS 8
#define THREADS (WARPS * 32)
#define MAXPART 2048

__device__ float2 g_part[MAXPART];
__device__ unsigned int g_done = 0;

__device__ __forceinline__ void tail(float dr, float u, float& acc, float& cnt)
{
    // dr = r_j - r_i (NaN if either invalid), u = s_j - s_i (finite)
    // one LOP3: u ^ (dr & signbit)
    const float vv = __uint_as_float(__float_as_uint(u) ^ (__float_as_uint(dr) & 0x80000000u));
    const float t  = fmaxf(vv + 1.0f, 0.0f);          // finite even for NaN dr
    const float wt = __saturatef(fabsf(dr));          // 0 on tie/invalid(NaN), 1 otherwise
    acc = fmaf(t, wt, acc);
    cnt += wt;
}

__global__ void __launch_bounds__(THREADS) pairloss_kernel(
    const float* __restrict__ scores,
    const int* __restrict__ rankings,
    const uint8_t* __restrict__ mask,
    float* __restrict__ out,
    int B, int nblocks)
{
    // per warp: entry t = (rank_{2t}, rank_{2t+1}, score_{2t}, score_{2t+1});
    // entries 32..47 duplicate 0..15 for wrap-free circular indexing
    __shared__ float4 sh[WARPS][48];
    __shared__ float2 sh_row[WARPS];
    __shared__ int s_last;

    const int lane = threadIdx.x & 31;
    const int w    = threadIdx.x >> 5;
    const int row  = blockIdx.x * WARPS + w;

    const float NaNf = __int_as_float(0x7fffffff);

    const int base = row * H + 2 * lane;
    const float2 sc = *reinterpret_cast<const float2*>(scores + base);
    const int2   rk = *reinterpret_cast<const int2*>(rankings + base);
    const uchar2 mk = *reinterpret_cast<const uchar2*>(mask + base);

    const float s0 = sc.x, s1 = sc.y;
    const bool  v0 = (mk.x != 0) && (rk.x > 0);
    const bool  v1 = (mk.y != 0) && (rk.y > 0);
    const float fr0 = v0 ? (float)rk.x : NaNf;   // invalid -> NaN rank: gates its pairs to 0
    const float fr1 = v1 ? (float)rk.y : NaNf;

    const float4 mine = make_float4(fr0, fr1, s0, s1);
    sh[w][lane] = mine;
    if (lane < 16) sh[w][lane + 32] = mine;
    __syncwarp();

    float accA = 0.f, cntA = 0.f, accB = 0.f, cntB = 0.f;

    // intra-group pair {2*lane, 2*lane+1}
    tail(fr1 - fr0, s1 - s0, accA, cntA);

    const float4* rowsh = sh[w];

    #pragma unroll
    for (int k = 1; k <= 15; ++k) {
        const float4 q = rowsh[lane + k];   // partner group (lane+k) mod 32: (ra, rb, sa, sb)
        tail(q.x - fr0, q.z - s0, accA, cntA);   // {2l,   2(l+k)  }
        tail(q.y - fr0, q.w - s0, accA, cntA);   // {2l,   2(l+k)+1}
        tail(q.x - fr1, q.z - s1, accB, cntB);   // {2l+1, 2(l+k)  }
        tail(q.y - fr1, q.w - s1, accB, cntB);   // {2l+1, 2(l+k)+1}
    }

    // k = 16: only lanes 0..15 own these group pairs (avoid double count)
    {
        const float4 q = rowsh[lane + 16];
        const float ra = (lane < 16) ? q.x : NaNf;   // NaN -> weight 0
        const float rb = (lane < 16) ? q.y : NaNf;
        tail(ra - fr0, q.z - s0, accA, cntA);
        tail(rb - fr0, q.w - s0, accA, cntA);
        tail(ra - fr1, q.z - s1, accB, cntB);
        tail(rb - fr1, q.w - s1, accB, cntB);
    }

    float acc = accA + accB;
    float cnt = cntA + cntB;
    #pragma unroll
    for (int o = 16; o > 0; o >>= 1) {
        acc += __shfl_down_sync(0xffffffffu, acc, o);
        cnt += __shfl_down_sync(0xffffffffu, cnt, o);
    }
    if (lane == 0) {
        sh_row[w] = make_float2((cnt > 0.f) ? (acc / cnt) : 0.f, (cnt > 0.f) ? 1.f : 0.f);
    }
    __syncthreads();

    if (threadIdx.x == 0) {
        float l = 0.f, h = 0.f;
        #pragma unroll
        for (int i = 0; i < WARPS; ++i) { l += sh_row[i].x; h += sh_row[i].y; }
        g_part[blockIdx.x] = make_float2(l, h);
        __threadfence();
        const unsigned int t = atomicAdd(&g_done, 1u);
        s_last = (t == (unsigned int)(nblocks - 1)) ? 1 : 0;
    }
    __syncthreads();

    // last block reduces all partials in FIXED index order -> deterministic
    if (s_last) {
        __threadfence();
        float l = 0.f, h = 0.f;
        for (int i = threadIdx.x; i < nblocks; i += THREADS) {
            const float2 p = g_part[i];
            l += p.x;
            h += p.y;
        }
        __shared__ float f_l[THREADS];
        __shared__ float f_h[THREADS];
        f_l[threadIdx.x] = l;
        f_h[threadIdx.x] = h;
        __syncthreads();
        #pragma unroll
        for (int s = THREADS / 2; s > 0; s >>= 1) {
            if (threadIdx.x < s) {
                f_l[threadIdx.x] += f_l[threadIdx.x + s];
                f_h[threadIdx.x] += f_h[threadIdx.x + s];
            }
            __syncthreads();
        }
        if (threadIdx.x == 0) {
            const float n = f_h[0];
            out[0] = (n > 0.f) ? (f_l[0] / n) : 0.f;
            g_done = 0;                      // reset for next graph replay
        }
    }
}

extern "C" void kernel_launch(void* const* d_in, const int* in_sizes, int n_in,
                              void* d_out, int out_size)
{
    const float*   scores   = (const float*)d_in[0];
    const int*     rankings = (const int*)d_in[1];
    const uint8_t* mask     = (const uint8_t*)d_in[2];
    float*         out      = (float*)d_out;

    const int B = in_sizes[0] / H;
    const int nblocks = (B + WARPS - 1) / WARPS;

    pairloss_kernel<<<nblocks, THREADS>>>(scores, rankings, mask, out, B, nblocks);
}

// round 15
// speedup vs baseline: 1.1117x; 1.1117x over previous
#include <cuda_runtime.h>
#include <stdint.h>
#include <math.h>

#define H 64
#define WARPS 8
#define THREADS (WARPS * 32)
#define MAXPART 2048

__device__ float2 g_part[MAXPART];
__device__ unsigned int g_done = 0;

typedef unsigned long long u64;

__device__ __forceinline__ u64 addf32x2(u64 a, u64 b)
{
    u64 r;
    asm("add.rn.f32x2 %0, %1, %2;" : "=l"(r) : "l"(a), "l"(b));
    return r;
}
// zero-SASS pack/unpack: u64 <-> register pair via casts
__device__ __forceinline__ u64 pk(float lo, float hi)
{
    return (u64)__float_as_uint(lo) | ((u64)__float_as_uint(hi) << 32);
}
__device__ __forceinline__ float lof(u64 v) { return __uint_as_float((unsigned)v); }
__device__ __forceinline__ float hif(u64 v) { return __uint_as_float((unsigned)(v >> 32)); }

__device__ __forceinline__ void tail(float dr, float u, float& acc, float& cnt)
{
    // dr = r_j - r_i (NaN if either invalid), u = s_j - s_i (finite)
    const float vv = __uint_as_float(__float_as_uint(u) ^ (__float_as_uint(dr) & 0x80000000u));
    const float t  = fmaxf(vv + 1.0f, 0.0f);          // finite even for NaN dr
    const float wt = __saturatef(fabsf(dr));          // 0 on tie/invalid(NaN), 1 otherwise
    acc = fmaf(t, wt, acc);
    cnt += wt;
}

__global__ void __launch_bounds__(THREADS, 4) pairloss_kernel(
    const float* __restrict__ scores,
    const int* __restrict__ rankings,
    const uint8_t* __restrict__ mask,
    float* __restrict__ out,
    int B, int nblocks)
{
    // per warp: entry t = (rank_{2t}, rank_{2t+1} | score_{2t}, score_{2t+1});
    // entries 32..47 duplicate 0..15 for wrap-free circular indexing
    __shared__ ulonglong2 sh[WARPS][48];
    __shared__ float2 sh_row[WARPS];
    __shared__ int s_last;

    const int lane = threadIdx.x & 31;
    const int w    = threadIdx.x >> 5;
    const int row  = blockIdx.x * WARPS + w;

    const float NaNf = __int_as_float(0x7fffffff);

    const int base = row * H + 2 * lane;
    const float2 sc = *reinterpret_cast<const float2*>(scores + base);
    const int2   rk = *reinterpret_cast<const int2*>(rankings + base);
    const uchar2 mk = *reinterpret_cast<const uchar2*>(mask + base);

    const float s0 = sc.x, s1 = sc.y;
    const bool  v0 = (mk.x != 0) && (rk.x > 0);
    const bool  v1 = (mk.y != 0) && (rk.y > 0);
    const float fr0 = v0 ? (float)rk.x : NaNf;   // invalid -> NaN rank: gates its pairs to 0
    const float fr1 = v1 ? (float)rk.y : NaNf;

    const ulonglong2 mine = make_ulonglong2(pk(fr0, fr1), pk(s0, s1));
    sh[w][lane] = mine;
    if (lane < 16) sh[w][lane + 32] = mine;
    __syncwarp();

    const u64 nr0 = pk(-fr0, -fr0);   // -NaN is still NaN
    const u64 nr1 = pk(-fr1, -fr1);
    const u64 ns0 = pk(-s0, -s0);
    const u64 ns1 = pk(-s1, -s1);

    float accA = 0.f, cntA = 0.f, accB = 0.f, cntB = 0.f;

    // intra-group pair {2*lane, 2*lane+1}
    tail(fr1 - fr0, s1 - s0, accA, cntA);

    const ulonglong2* p = &sh[w][lane];

    #pragma unroll
    for (int k = 1; k <= 15; ++k) {
        const ulonglong2 q = p[k];                  // partner group (lane+k) mod 32
        const u64 dra = addf32x2(q.x, nr0);         // (ra - fr0, rb - fr0)
        const u64 drb = addf32x2(q.x, nr1);         // (ra - fr1, rb - fr1)
        const u64 ua  = addf32x2(q.y, ns0);
        const u64 ub  = addf32x2(q.y, ns1);
        tail(lof(dra), lof(ua), accA, cntA);
        tail(hif(dra), hif(ua), accA, cntA);
        tail(lof(drb), lof(ub), accB, cntB);
        tail(hif(drb), hif(ub), accB, cntB);
    }

    // k = 16: only lanes 0..15 own these group pairs (avoid double count)
    {
        const ulonglong2 q = p[16];
        const u64 qr = (lane < 16) ? q.x : pk(NaNf, NaNf);   // NaN -> weight 0
        const u64 dra = addf32x2(qr, nr0);
        const u64 drb = addf32x2(qr, nr1);
        const u64 ua  = addf32x2(q.y, ns0);
        const u64 ub  = addf32x2(q.y, ns1);
        tail(lof(dra), lof(ua), accA, cntA);
        tail(hif(dra), hif(ua), accA, cntA);
        tail(lof(drb), lof(ub), accB, cntB);
        tail(hif(drb), hif(ub), accB, cntB);
    }

    float acc = accA + accB;
    float cnt = cntA + cntB;
    #pragma unroll
    for (int o = 16; o > 0; o >>= 1) {
        acc += __shfl_down_sync(0xffffffffu, acc, o);
        cnt += __shfl_down_sync(0xffffffffu, cnt, o);
    }
    if (lane == 0) {
        sh_row[w] = make_float2((cnt > 0.f) ? (acc / cnt) : 0.f, (cnt > 0.f) ? 1.f : 0.f);
    }
    __syncthreads();

    if (threadIdx.x == 0) {
        float l = 0.f, h = 0.f;
        #pragma unroll
        for (int i = 0; i < WARPS; ++i) { l += sh_row[i].x; h += sh_row[i].y; }
        g_part[blockIdx.x] = make_float2(l, h);
        __threadfence();
        const unsigned int t = atomicAdd(&g_done, 1u);
        s_last = (t == (unsigned int)(nblocks - 1)) ? 1 : 0;
    }
    __syncthreads();

    // last block reduces all partials in FIXED index order -> deterministic
    if (s_last) {
        __threadfence();
        float l = 0.f, h = 0.f;
        for (int i = threadIdx.x; i < nblocks; i += THREADS) {
            const float2 pp = g_part[i];
            l += pp.x;
            h += pp.y;
        }
        __shared__ float f_l[THREADS];
        __shared__ float f_h[THREADS];
        f_l[threadIdx.x] = l;
        f_h[threadIdx.x] = h;
        __syncthreads();
        #pragma unroll
        for (int s = THREADS / 2; s > 0; s >>= 1) {
            if (threadIdx.x < s) {
                f_l[threadIdx.x] += f_l[threadIdx.x + s];
                f_h[threadIdx.x] += f_h[threadIdx.x + s];
            }
            __syncthreads();
        }
        if (threadIdx.x == 0) {
            const float n = f_h[0];
            out[0] = (n > 0.f) ? (f_l[0] / n) : 0.f;
            g_done = 0;                      // reset for next graph replay
        }
    }
}

extern "C" void kernel_launch(void* const* d_in, const int* in_sizes, int n_in,
                              void* d_out, int out_size)
{
    const float*   scores   = (const float*)d_in[0];
    const int*     rankings = (const int*)d_in[1];
    const uint8_t* mask     = (const uint8_t*)d_in[2];
    float*         out      = (float*)d_out;

    const int B = in_sizes[0] / H;
    const int nblocks = (B + WARPS - 1) / WARPS;

    pairloss_kernel<<<nblocks, THREADS>>>(scores, rankings, mask, out, B, nblocks);
}

// round 16
// speedup vs baseline: 1.1307x; 1.0170x over previous
#include <cuda_runtime.h>
#include <stdint.h>
#include <math.h>

#define H 64
#define WARPS 8
#define THREADS (WARPS * 32)
#define MAXPART 2048
#define GSHIFT 7               // 128 blocks per group
#define GSIZE (1 << GSHIFT)
#define MAXGROUPS 16

__device__ float2 g_part[MAXPART];
__device__ float2 g_gpart[MAXGROUPS];
__device__ unsigned int g_gdone[MAXGROUPS];   // zero-init
__device__ unsigned int g_fdone = 0;

typedef unsigned long long u64;

__device__ __forceinline__ u64 addf32x2(u64 a, u64 b)
{
    u64 r;
    asm("add.rn.f32x2 %0, %1, %2;" : "=l"(r) : "l"(a), "l"(b));
    return r;
}
__device__ __forceinline__ u64 pk(float lo, float hi)
{
    u64 r;
    asm("mov.b64 %0, {%1, %2};" : "=l"(r) : "f"(lo), "f"(hi));
    return r;
}
__device__ __forceinline__ void upk(u64 v, float& lo, float& hi)
{
    asm("mov.b64 {%0, %1}, %2;" : "=f"(lo), "=f"(hi) : "l"(v));
}

__device__ __forceinline__ void tail(float dr, float u, float& acc, float& cnt)
{
    // dr = r_j - r_i (NaN if either invalid), u = s_j - s_i (finite)
    const float vv = __uint_as_float(__float_as_uint(u) ^ (__float_as_uint(dr) & 0x80000000u));
    const float t  = fmaxf(vv + 1.0f, 0.0f);          // finite even for NaN dr
    const float wt = __saturatef(fabsf(dr));          // 0 on tie/invalid(NaN), 1 otherwise
    acc = fmaf(t, wt, acc);
    cnt += wt;
}

__global__ void __launch_bounds__(THREADS) pairloss_kernel(
    const float* __restrict__ scores,
    const int* __restrict__ rankings,
    const uint8_t* __restrict__ mask,
    float* __restrict__ out,
    int B, int nblocks, int ngroups)
{
    __shared__ ulonglong2 sh[WARPS][48];
    __shared__ float2 sh_row[WARPS];
    __shared__ float2 sh_wred[4];
    __shared__ int s_glast, s_flast;

    const int lane = threadIdx.x & 31;
    const int w    = threadIdx.x >> 5;
    const int row  = blockIdx.x * WARPS + w;

    const float NaNf = __int_as_float(0x7fffffff);

    const int base = row * H + 2 * lane;
    const float2 sc = *reinterpret_cast<const float2*>(scores + base);
    const int2   rk = *reinterpret_cast<const int2*>(rankings + base);
    const uchar2 mk = *reinterpret_cast<const uchar2*>(mask + base);

    const float s0 = sc.x, s1 = sc.y;
    const bool  v0 = (mk.x != 0) && (rk.x > 0);
    const bool  v1 = (mk.y != 0) && (rk.y > 0);
    const float fr0 = v0 ? (float)rk.x : NaNf;   // invalid -> NaN rank: gates its pairs to 0
    const float fr1 = v1 ? (float)rk.y : NaNf;

    const ulonglong2 mine = make_ulonglong2(pk(fr0, fr1), pk(s0, s1));
    sh[w][lane] = mine;
    if (lane < 16) sh[w][lane + 32] = mine;
    __syncwarp();

    const u64 nr0 = pk(-fr0, -fr0);   // -NaN is still NaN
    const u64 nr1 = pk(-fr1, -fr1);
    const u64 ns0 = pk(-s0, -s0);
    const u64 ns1 = pk(-s1, -s1);

    float accA = 0.f, cntA = 0.f, accB = 0.f, cntB = 0.f;

    // intra-group pair {2*lane, 2*lane+1}
    tail(fr1 - fr0, s1 - s0, accA, cntA);

    const ulonglong2* p = &sh[w][lane];

    #pragma unroll
    for (int k = 1; k <= 15; ++k) {
        const ulonglong2 q = p[k];                  // partner group (lane+k) mod 32
        const u64 dra = addf32x2(q.x, nr0);
        const u64 drb = addf32x2(q.x, nr1);
        const u64 ua  = addf32x2(q.y, ns0);
        const u64 ub  = addf32x2(q.y, ns1);
        float d0, d1, d2, d3, x0, x1, x2, x3;
        upk(dra, d0, d1); upk(drb, d2, d3);
        upk(ua,  x0, x1); upk(ub,  x2, x3);
        tail(d0, x0, accA, cntA);
        tail(d1, x1, accA, cntA);
        tail(d2, x2, accB, cntB);
        tail(d3, x3, accB, cntB);
    }

    // k = 16: only lanes 0..15 own these group pairs (avoid double count)
    {
        const ulonglong2 q = p[16];
        const u64 qr = (lane < 16) ? q.x : pk(NaNf, NaNf);
        const u64 dra = addf32x2(qr, nr0);
        const u64 drb = addf32x2(qr, nr1);
        const u64 ua  = addf32x2(q.y, ns0);
        const u64 ub  = addf32x2(q.y, ns1);
        float d0, d1, d2, d3, x0, x1, x2, x3;
        upk(dra, d0, d1); upk(drb, d2, d3);
        upk(ua,  x0, x1); upk(ub,  x2, x3);
        tail(d0, x0, accA, cntA);
        tail(d1, x1, accA, cntA);
        tail(d2, x2, accB, cntB);
        tail(d3, x3, accB, cntB);
    }

    float acc = accA + accB;
    float cnt = cntA + cntB;
    #pragma unroll
    for (int o = 16; o > 0; o >>= 1) {
        acc += __shfl_down_sync(0xffffffffu, acc, o);
        cnt += __shfl_down_sync(0xffffffffu, cnt, o);
    }
    if (lane == 0) {
        sh_row[w] = make_float2((cnt > 0.f) ? (acc / cnt) : 0.f, (cnt > 0.f) ? 1.f : 0.f);
    }
    __syncthreads();

    const int gid    = blockIdx.x >> GSHIFT;
    const int gfirst = gid << GSHIFT;
    const int gcount = min(GSIZE, nblocks - gfirst);

    if (threadIdx.x == 0) {
        float l = 0.f, h = 0.f;
        #pragma unroll
        for (int i = 0; i < WARPS; ++i) { l += sh_row[i].x; h += sh_row[i].y; }
        g_part[blockIdx.x] = make_float2(l, h);
        __threadfence();
        const unsigned int t = atomicAdd(&g_gdone[gid], 1u);
        s_glast = (t == (unsigned int)(gcount - 1)) ? 1 : 0;
    }
    __syncthreads();

    // ---- level 1: group-last block reduces its <=128 partials (fixed order) ----
    if (s_glast) {
        __threadfence();
        float l = 0.f, h = 0.f;
        if ((int)threadIdx.x < gcount) {
            const float2 pp = g_part[gfirst + threadIdx.x];
            l = pp.x; h = pp.y;
        }
        #pragma unroll
        for (int o = 16; o > 0; o >>= 1) {
            l += __shfl_down_sync(0xffffffffu, l, o);
            h += __shfl_down_sync(0xffffffffu, h, o);
        }
        if (lane == 0 && w < 4) sh_wred[w] = make_float2(l, h);
        __syncthreads();
        if (threadIdx.x == 0) {
            float gl = 0.f, gh = 0.f;
            #pragma unroll
            for (int i = 0; i < 4; ++i) { gl += sh_wred[i].x; gh += sh_wred[i].y; }
            g_gpart[gid] = make_float2(gl, gh);
            __threadfence();
            const unsigned int t2 = atomicAdd(&g_fdone, 1u);
            s_flast = (t2 == (unsigned int)(ngroups - 1)) ? 1 : 0;
        }
        __syncthreads();

        // ---- level 2: globally-last group reduces <=16 group partials ----
        if (s_flast) {
            if (w == 0) {
                __threadfence();
                float l2 = 0.f, h2 = 0.f;
                if (lane < ngroups) {
                    const float2 gp = g_gpart[lane];
                    l2 = gp.x; h2 = gp.y;
                }
                #pragma unroll
                for (int o = 16; o > 0; o >>= 1) {
                    l2 += __shfl_down_sync(0xffffffffu, l2, o);
                    h2 += __shfl_down_sync(0xffffffffu, h2, o);
                }
                if (lane == 0) {
                    out[0] = (h2 > 0.f) ? (l2 / h2) : 0.f;
                    g_fdone = 0;                       // reset for next graph replay
                }
                if (lane < MAXGROUPS) g_gdone[lane] = 0;
            }
        }
    }
}

extern "C" void kernel_launch(void* const* d_in, const int* in_sizes, int n_in,
                              void* d_out, int out_size)
{
    const float*   scores   = (const float*)d_in[0];
    const int*     rankings = (const int*)d_in[1];
    const uint8_t* mask     = (const uint8_t*)d_in[2];
    float*         out      = (float*)d_out;

    const int B = in_sizes[0] / H;
    const int nblocks = (B + WARPS - 1) / WARPS;
    const int ngroups = (nblocks + GSIZE - 1) >> GSHIFT;

    pairloss_kernel<<<nblocks, THREADS>>>(scores, rankings, mask, out, B, nblocks, ngroups);
}